// round 13
// baseline (speedup 1.0000x reference)
#include <cuda_runtime.h>
#include <cstdint>
#include <math.h>

// GumbelSlotSelector — mma.sync TF32 3-split GEMM (legacy tensor path, no 'a' features)
// + exact-fp32 near-tie cleanup.  B=256, K=512, D=256, H=256.

static constexpr int B_   = 256;
static constexpr int K_   = 512;
static constexpr int BK   = B_ * K_;      // 131072 rows
static constexpr int D_   = 256;
static constexpr int H_   = 256;
static constexpr int MT   = 128;          // rows per block
static constexpr int NBLK = BK / MT;      // 1024 blocks
static constexpr int BPB  = K_ / MT;      // fused blocks per batch = 4
static constexpr int XSTR = 260;          // xs row stride (floats): (260*g)%32=4g -> conflict-free frags
static constexpr int KPAD = 36;           // B chunk k-stride: (36*g+tig)%32 covers 32 banks
static constexpr float LN_EPS  = 1e-5f;
static constexpr float TIE_EPS = 2e-2f;   // near-tie gumbel gap -> exact recompute

__device__ int g_partial[NBLK];
__device__ int g_tie_n;
__device__ int g_tie_rows[BK];
// B splits, layout [kc(8)][n(256)][kin(36)] of tf32-bit floats (cp.async-ready, 16B aligned)
__device__ __align__(16) uint32_t g_Bh[8 * 256 * KPAD];
__device__ __align__(16) uint32_t g_Bl[8 * 256 * KPAD];

struct __align__(16) Smem {
    float  bbuf[2][256 * KPAD];   // 2 x 36KB B chunk double buffer
    float  xs[MT * XSTR];         // LN'd activations (padded rows): 133KB
    float  mu[MT], rs[MT];
    float  gs[D_], bs[D_], b1s[H_];
    float2 w2s[H_];
    float  pp0[2 * MT], pp1[2 * MT];
    int    cnt;
};                                // ~215KB

__device__ __forceinline__ void cp16(void* s, const void* g) {
    uint32_t sa = (uint32_t)__cvta_generic_to_shared(s);
    asm volatile("cp.async.cg.shared.global [%0], [%1], 16;" :: "r"(sa), "l"(g));
}
__device__ __forceinline__ void cp_commit() { asm volatile("cp.async.commit_group;"); }
template <int N>
__device__ __forceinline__ void cp_wait() { asm volatile("cp.async.wait_group %0;" :: "n"(N)); }

__device__ __forceinline__ uint32_t f2tf32(float x) {
    uint32_t r; asm("cvt.rna.tf32.f32 %0, %1;" : "=r"(r) : "f"(x)); return r;
}
// D += A(tf32 m16k8 row) * B(tf32 k8n8 col)
__device__ __forceinline__ void mma8(float* c, const uint32_t* a, uint32_t b0, uint32_t b1) {
    asm volatile("mma.sync.aligned.m16n8k8.row.col.f32.tf32.tf32.f32 "
                 "{%0,%1,%2,%3}, {%4,%5,%6,%7}, {%8,%9}, {%0,%1,%2,%3};"
                 : "+f"(c[0]), "+f"(c[1]), "+f"(c[2]), "+f"(c[3])
                 : "r"(a[0]), "r"(a[1]), "r"(a[2]), "r"(a[3]), "r"(b0), "r"(b1));
}

// ---------------- prep: TF32 hi/lo B splits in fragment-friendly layout ----------------
__global__ void __launch_bounds__(256) prep_kernel(const float* __restrict__ w1) {
    int k = blockIdx.x, n = threadIdx.x;          // B[n][k] = W1[k][n]
    float x = w1[k * H_ + n];
    uint32_t hi = f2tf32(x);
    uint32_t lo = f2tf32(x - __uint_as_float(hi));
    int kc = k >> 5, kin = k & 31;
    g_Bh[(kc * 256 + n) * KPAD + kin] = hi;
    g_Bl[(kc * 256 + n) * KPAD + kin] = lo;
    if (k == 0 && n == 0) g_tie_n = 0;
}

// ---------------- fused: LN + 3-pass TF32 mma.sync GEMM + epilogue ----------------
__global__ void __launch_bounds__(256, 1) fused_kernel(
    const float* __restrict__ slots,
    const float* __restrict__ lng,
    const float* __restrict__ lnb,
    const float* __restrict__ b1,
    const float* __restrict__ w2,
    const float* __restrict__ b2,
    const float* __restrict__ uu,
    float* __restrict__ out_hard,
    float* __restrict__ out_soft)
{
    extern __shared__ char smraw[];
    Smem& sm = *reinterpret_cast<Smem*>(smraw);
    const int tid  = threadIdx.x;
    const int lane = tid & 31, wid = tid >> 5;
    const int base_row = blockIdx.x * MT;

    // ---- stage: xs (group0), B chunk0 (group1), B chunk1 (group2) ----
    {
        const float4* src = reinterpret_cast<const float4*>(slots) + (size_t)base_row * (D_ / 4);
        #pragma unroll
        for (int t = 0; t < 32; t++) {
            int idx = tid + t * 256;               // 8192 float4
            int row = idx >> 6, c4 = idx & 63;
            cp16(&sm.xs[row * XSTR + c4 * 4], &src[idx]);
        }
        cp_commit();
        const float4* bh = reinterpret_cast<const float4*>(g_Bh);
        float4* d0 = reinterpret_cast<float4*>(sm.bbuf[0]);
        float4* d1 = reinterpret_cast<float4*>(sm.bbuf[1]);
        #pragma unroll
        for (int t = 0; t < 9; t++) cp16(&d0[tid + t * 256], &bh[0 * 2304 + tid + t * 256]);
        cp_commit();
        #pragma unroll
        for (int t = 0; t < 9; t++) cp16(&d1[tid + t * 256], &bh[1 * 2304 + tid + t * 256]);
        cp_commit();
    }
    sm.gs[tid]  = lng[tid];
    sm.bs[tid]  = lnb[tid];
    sm.b1s[tid] = b1[tid];
    sm.w2s[tid] = make_float2(w2[2 * tid], w2[2 * tid + 1]);
    if (tid == 0) sm.cnt = 0;

    cp_wait<2>();              // xs arrived
    __syncthreads();

    // ---- LayerNorm ----
    for (int r = wid; r < MT; r += 8) {
        const float* row = sm.xs + r * XSTR;
        float s = 0.f;
        #pragma unroll
        for (int m = 0; m < 8; m++) s += row[lane + m * 32];
        #pragma unroll
        for (int o = 16; o; o >>= 1) s += __shfl_xor_sync(0xffffffffu, s, o);
        float mean = s * (1.f / D_);
        float v = 0.f;
        #pragma unroll
        for (int m = 0; m < 8; m++) { float d = row[lane + m * 32] - mean; v = fmaf(d, d, v); }
        #pragma unroll
        for (int o = 16; o; o >>= 1) v += __shfl_xor_sync(0xffffffffu, v, o);
        if (lane == 0) { sm.mu[r] = mean; sm.rs[r] = 1.f / sqrtf(v * (1.f / D_) + LN_EPS); }
    }
    __syncthreads();
    #pragma unroll 4
    for (int r = 0; r < MT; r++) {
        int idx = r * XSTR + tid;
        float vx = sm.xs[idx];
        sm.xs[idx] = (vx - sm.mu[r]) * sm.rs[r] * sm.gs[tid] + sm.bs[tid];
    }
    __syncthreads();

    // ---- GEMM1: warp tile 32 rows x 128 cols; fragments per mma.m16n8k8 layout ----
    const int g = lane >> 2, tig = lane & 3;       // groupID, thread-in-group
    const int mrow0 = (wid & 3) * 32;              // warp row base
    const int ncol0 = (wid >> 2) * 128;            // warp col base
    float acc[2][16][4];
    #pragma unroll
    for (int mt = 0; mt < 2; mt++)
        #pragma unroll
        for (int nt = 0; nt < 16; nt++)
            #pragma unroll
            for (int q = 0; q < 4; q++) acc[mt][nt][q] = 0.f;

    // 24 chunks = seg(3: Ah*Bh, Ah*Bl, Al*Bh) x kc(8)
    for (int s = 0; s < 24; s++) {
        const int b = s & 1;
        if (s == 23) cp_wait<0>(); else cp_wait<1>();
        __syncthreads();

        const int seg = s >> 3, kc = s & 7;
        const uint32_t* bb = reinterpret_cast<const uint32_t*>(sm.bbuf[b]);
        const float* xw = sm.xs;

        #pragma unroll
        for (int kk = 0; kk < 32; kk += 8) {
            uint32_t a[2][4];
            #pragma unroll
            for (int mt = 0; mt < 2; mt++) {
                int r0 = (mrow0 + mt * 16 + g) * XSTR;
                int c0 = kc * 32 + kk + tig;
                float x0 = xw[r0 + c0];
                float x1 = xw[r0 + 8 * XSTR + c0];
                float x2 = xw[r0 + c0 + 4];
                float x3 = xw[r0 + 8 * XSTR + c0 + 4];
                if (seg == 2) {        // A_lo
                    uint32_t h0 = f2tf32(x0), h1 = f2tf32(x1), h2 = f2tf32(x2), h3 = f2tf32(x3);
                    a[mt][0] = f2tf32(x0 - __uint_as_float(h0));
                    a[mt][1] = f2tf32(x1 - __uint_as_float(h1));
                    a[mt][2] = f2tf32(x2 - __uint_as_float(h2));
                    a[mt][3] = f2tf32(x3 - __uint_as_float(h3));
                } else {               // A_hi
                    a[mt][0] = f2tf32(x0);
                    a[mt][1] = f2tf32(x1);
                    a[mt][2] = f2tf32(x2);
                    a[mt][3] = f2tf32(x3);
                }
            }
            #pragma unroll
            for (int nt = 0; nt < 16; nt++) {
                int nc = (ncol0 + nt * 8 + g) * KPAD;
                uint32_t b0 = bb[nc + kk + tig];
                uint32_t b1r = bb[nc + kk + tig + 4];
                mma8(acc[0][nt], a[0], b0, b1r);
                mma8(acc[1][nt], a[1], b0, b1r);
            }
        }
        __syncthreads();

        if (s + 2 < 24) {              // prefetch chunk s+2 into the just-freed buffer
            int ns = s + 2, nseg = ns >> 3, nkc = ns & 7;
            const float4* src = reinterpret_cast<const float4*>(nseg == 1 ? g_Bl : g_Bh)
                              + nkc * 2304;
            float4* dst = reinterpret_cast<float4*>(sm.bbuf[b]);
            #pragma unroll
            for (int t = 0; t < 9; t++) cp16(&dst[tid + t * 256], &src[tid + t * 256]);
            cp_commit();
        }
    }

    // ---- epilogue: relu+b1, dot w2, quad-reduce, finalize ----
    {
        float p0[4] = {0.f, 0.f, 0.f, 0.f}, p1[4] = {0.f, 0.f, 0.f, 0.f};
        #pragma unroll
        for (int mt = 0; mt < 2; mt++)
            #pragma unroll
            for (int nt = 0; nt < 16; nt++)
                #pragma unroll
                for (int q = 0; q < 4; q++) {
                    int half = q >> 1;
                    int cc = ncol0 + nt * 8 + tig * 2 + (q & 1);
                    float h = fmaxf(acc[mt][nt][q] + sm.b1s[cc], 0.f);
                    float2 w = sm.w2s[cc];
                    int rr = mt * 2 + half;
                    p0[rr] = fmaf(h, w.x, p0[rr]);
                    p1[rr] = fmaf(h, w.y, p1[rr]);
                }
        #pragma unroll
        for (int rr = 0; rr < 4; rr++) {
            p0[rr] += __shfl_xor_sync(0xffffffffu, p0[rr], 1);
            p0[rr] += __shfl_xor_sync(0xffffffffu, p0[rr], 2);
            p1[rr] += __shfl_xor_sync(0xffffffffu, p1[rr], 1);
            p1[rr] += __shfl_xor_sync(0xffffffffu, p1[rr], 2);
        }
        if (tig == 0) {
            #pragma unroll
            for (int rr = 0; rr < 4; rr++) {
                int row_local = mrow0 + (rr >> 1) * 16 + (rr & 1) * 8 + g;
                sm.pp0[(wid >> 2) * 128 + row_local] = p0[rr];
                sm.pp1[(wid >> 2) * 128 + row_local] = p1[rr];
            }
        }
    }
    __syncthreads();

    int myhard = 0;
    if (tid < 128) {
        int row = base_row + tid;
        float l0 = sm.pp0[tid] + sm.pp0[128 + tid] + b2[0];
        float l1 = sm.pp1[tid] + sm.pp1[128 + tid] + b2[1];
        float soft = 1.f / (1.f + expf(l0 - l1));
        float u0 = uu[2 * row], u1 = uu[2 * row + 1];
        float z0 = l0 - logf(-logf(u0));
        float z1 = l1 - logf(-logf(u1));
        int hard = (z1 > z0) ? 1 : 0;
        out_hard[row] = (float)hard;
        out_soft[row] = soft;
        myhard = hard;
        if (fabsf(z1 - z0) < TIE_EPS) {
            int ix = atomicAdd(&g_tie_n, 1);
            g_tie_rows[ix] = row;
        }
    }
    unsigned mvote = __ballot_sync(0xffffffffu, myhard != 0);
    if (lane == 0) atomicAdd(&sm.cnt, __popc(mvote));
    __syncthreads();
    if (tid == 0) g_partial[blockIdx.x] = sm.cnt;
}

// ---------------- cleanup: exact fp32 recompute of near-tie rows ----------------
__global__ void __launch_bounds__(256) cleanup_kernel(
    const float* __restrict__ slots, const float* __restrict__ lng,
    const float* __restrict__ lnb,   const float* __restrict__ w1,
    const float* __restrict__ b1,    const float* __restrict__ w2,
    const float* __restrict__ b2,    const float* __restrict__ uu,
    float* __restrict__ out_hard,    float* __restrict__ out_soft)
{
    __shared__ float xln[256];
    __shared__ float wr[8], l0s[8], l1s[8];
    const int t = threadIdx.x, lane = t & 31, w = t >> 5;
    const int n = g_tie_n;
    for (int ii = blockIdx.x; ii < n; ii += gridDim.x) {
        int row = g_tie_rows[ii];
        float v = slots[(size_t)row * D_ + t];
        float s = v;
        #pragma unroll
        for (int o = 16; o; o >>= 1) s += __shfl_xor_sync(0xffffffffu, s, o);
        if (lane == 0) wr[w] = s;
        __syncthreads();
        float tot = 0.f;
        #pragma unroll
        for (int j = 0; j < 8; j++) tot += wr[j];
        float mean = tot * (1.f / 256);
        __syncthreads();
        float d = v - mean, s2 = d * d;
        #pragma unroll
        for (int o = 16; o; o >>= 1) s2 += __shfl_xor_sync(0xffffffffu, s2, o);
        if (lane == 0) wr[w] = s2;
        __syncthreads();
        float vt = 0.f;
        #pragma unroll
        for (int j = 0; j < 8; j++) vt += wr[j];
        float rstd = 1.f / sqrtf(vt * (1.f / 256) + LN_EPS);
        xln[t] = (v - mean) * rstd * lng[t] + lnb[t];
        __syncthreads();
        float acc = b1[t];
        for (int k = 0; k < 256; k++) acc = fmaf(xln[k], w1[k * 256 + t], acc);
        float h = fmaxf(acc, 0.f);
        float q0 = h * w2[2 * t], q1 = h * w2[2 * t + 1];
        #pragma unroll
        for (int o = 16; o; o >>= 1) {
            q0 += __shfl_xor_sync(0xffffffffu, q0, o);
            q1 += __shfl_xor_sync(0xffffffffu, q1, o);
        }
        if (lane == 0) { l0s[w] = q0; l1s[w] = q1; }
        __syncthreads();
        if (t == 0) {
            float l0 = b2[0], l1 = b2[1];
            #pragma unroll
            for (int j = 0; j < 8; j++) { l0 += l0s[j]; l1 += l1s[j]; }
            float soft = 1.f / (1.f + expf(l0 - l1));
            float u0 = uu[2 * row], u1 = uu[2 * row + 1];
            float z0 = l0 - logf(-logf(u0));
            float z1 = l1 - logf(-logf(u1));
            int hard = (z1 > z0) ? 1 : 0;
            int oldh = (out_hard[row] != 0.f) ? 1 : 0;
            if (hard != oldh) {
                out_hard[row] = (float)hard;
                atomicAdd(&g_partial[row >> 7], hard - oldh);
            }
            out_soft[row] = soft;
        }
        __syncthreads();
    }
}

// ---------------- resample: lower-bound fixup ----------------
__global__ void __launch_bounds__(256) resample_kernel(
    const float* __restrict__ rk, float* __restrict__ out_hard)
{
    __shared__ float vs[256];
    __shared__ int   is_[256];
    const int b = blockIdx.x, tid = threadIdx.x;
    int kept = 0;
    #pragma unroll
    for (int j = 0; j < BPB; j++) kept += g_partial[b * BPB + j];
    if (kept > 0) return;
    const float* r = rk + b * K_;
    float v0 = r[tid], v1 = r[tid + 256];
    float v; int idx;
    if (v0 >= v1) { v = v0; idx = tid; } else { v = v1; idx = tid + 256; }
    vs[tid] = v; is_[tid] = idx;
    __syncthreads();
    for (int s = 128; s; s >>= 1) {
        if (tid < s) {
            float ov = vs[tid + s]; int oi = is_[tid + s];
            if (ov > vs[tid] || (ov == vs[tid] && oi < is_[tid])) { vs[tid] = ov; is_[tid] = oi; }
        }
        __syncthreads();
    }
    if (tid == 0) out_hard[b * K_ + is_[0]] = 1.f;
}

extern "C" void kernel_launch(void* const* d_in, const int* in_sizes, int n_in,
                              void* d_out, int out_size)
{
    const float* slots = (const float*)d_in[0];
    const float* lng   = (const float*)d_in[1];
    const float* lnb   = (const float*)d_in[2];
    const float* w1    = (const float*)d_in[3];
    const float* b1    = (const float*)d_in[4];
    const float* w2    = (const float*)d_in[5];
    const float* b2    = (const float*)d_in[6];
    const float* uu    = (const float*)d_in[7];
    const float* rk    = (const float*)d_in[8];
    float* out_hard = (float*)d_out;
    float* out_soft = out_hard + BK;

    cudaFuncSetAttribute(fused_kernel,
                         cudaFuncAttributeMaxDynamicSharedMemorySize,
                         (int)sizeof(Smem));

    prep_kernel<<<256, 256>>>(w1);
    fused_kernel<<<NBLK, 256, sizeof(Smem)>>>(slots, lng, lnb, b1, w2, b2,
                                              uu, out_hard, out_soft);
    cleanup_kernel<<<64, 256>>>(slots, lng, lnb, w1, b1, w2, b2, uu,
                                out_hard, out_soft);
    resample_kernel<<<B_, 256>>>(rk, out_hard);
}

// round 14
// speedup vs baseline: 1.8156x; 1.8156x over previous
#include <cuda_runtime.h>
#include <cstdint>
#include <math.h>

// GumbelSlotSelector — dual-pipe hybrid: warps 0-3 legacy mma.sync TF32 3-split
// (rows 0-63/tile), warps 4-7 packed fma.rn.f32x2 exact fp32 (rows 64-127/tile).
// Near-tie tensor rows get exact fp32 recompute.  B=256,K=512,D=256,H=256.

static constexpr int B_   = 256;
static constexpr int K_   = 512;
static constexpr int BK   = B_ * K_;
static constexpr int D_   = 256;
static constexpr int H_   = 256;
static constexpr int MT   = 128;
static constexpr int NBLK = BK / MT;      // 1024
static constexpr int BPB  = K_ / MT;      // 4
static constexpr int XSTR = 260;          // xs row stride: (260g+c)%32 conflict-free patterns
static constexpr int KCHF = 16;           // fma W chunk k-size
static constexpr int NCHF = D_ / KCHF;    // 16 chunks
static constexpr int KCHT = 16;           // tensor B chunk k-size
static constexpr int KPADT = 20;          // tensor B k-stride: (20g+tig)%32 covers 32 banks
static constexpr int NCHT = 3 * (D_ / KCHT);  // 48 chunks = seg(3) x kc(16)
static constexpr float LN_EPS  = 1e-5f;
static constexpr float TIE_EPS = 2e-2f;

__device__ int g_partial[NBLK];
__device__ int g_tie_n;
__device__ int g_tie_rows[BK];
// tensor B splits: [kc(16)][n(256)][kin(KPADT)]
__device__ __align__(16) uint32_t g_Bh[16 * 256 * KPADT];
__device__ __align__(16) uint32_t g_Bl[16 * 256 * KPADT];

struct __align__(16) Smem {
    float  bufF[2][KCHF * H_];     // fma W f32 chunks: 2 x 16KB
    float  bufT[2][256 * KPADT];   // tensor B tf32 chunks: 2 x 20KB
    float  xs[MT * XSTR];          // 133KB
    float  mu[MT], rs[MT];
    float  gs[D_], bs[D_], b1s[H_];
    float2 w2s[H_];
    int    cnt;
};                                 // ~211KB

__device__ __forceinline__ void cp16(void* s, const void* g) {
    uint32_t sa = (uint32_t)__cvta_generic_to_shared(s);
    asm volatile("cp.async.cg.shared.global [%0], [%1], 16;" :: "r"(sa), "l"(g));
}
__device__ __forceinline__ void cp_commit() { asm volatile("cp.async.commit_group;"); }
template <int N>
__device__ __forceinline__ void cp_wait() { asm volatile("cp.async.wait_group %0;" :: "n"(N)); }
__device__ __forceinline__ void barx(int id) {
    asm volatile("bar.sync %0, 128;" :: "r"(id) : "memory");
}
__device__ __forceinline__ uint32_t f2tf32(float x) {
    uint32_t r; asm("cvt.rna.tf32.f32 %0, %1;" : "=r"(r) : "f"(x)); return r;
}
__device__ __forceinline__ void mma8(float* c, const uint32_t* a, uint32_t b0, uint32_t b1) {
    asm volatile("mma.sync.aligned.m16n8k8.row.col.f32.tf32.tf32.f32 "
                 "{%0,%1,%2,%3}, {%4,%5,%6,%7}, {%8,%9}, {%0,%1,%2,%3};"
                 : "+f"(c[0]), "+f"(c[1]), "+f"(c[2]), "+f"(c[3])
                 : "r"(a[0]), "r"(a[1]), "r"(a[2]), "r"(a[3]), "r"(b0), "r"(b1));
}
__device__ __forceinline__ void ffma2(unsigned long long& d,
                                      unsigned long long a, unsigned long long b) {
    asm("fma.rn.f32x2 %0, %1, %2, %0;" : "+l"(d) : "l"(a), "l"(b));
}
__device__ __forceinline__ unsigned long long bcast2(float a) {
    unsigned long long r;
    asm("mov.b64 %0, {%1, %1};" : "=l"(r) : "f"(a));
    return r;
}

// ---------------- prep: TF32 hi/lo B splits ----------------
__global__ void __launch_bounds__(256) prep_kernel(const float* __restrict__ w1) {
    int k = blockIdx.x, n = threadIdx.x;          // k in 0..255
    float x = w1[k * H_ + n];                     // B[n][k] = W1[k][n]
    uint32_t hi = f2tf32(x);
    uint32_t lo = f2tf32(x - __uint_as_float(hi));
    int kc = k >> 4, kin = k & 15;
    g_Bh[(kc * 256 + n) * KPADT + kin] = hi;
    g_Bl[(kc * 256 + n) * KPADT + kin] = lo;
    if (k == 0 && n == 0) g_tie_n = 0;
}

// ---------------- fused hybrid kernel ----------------
__global__ void __launch_bounds__(256, 1) fused_kernel(
    const float* __restrict__ slots,
    const float* __restrict__ lng,
    const float* __restrict__ lnb,
    const float* __restrict__ w1,
    const float* __restrict__ b1,
    const float* __restrict__ w2,
    const float* __restrict__ b2,
    const float* __restrict__ uu,
    float* __restrict__ out_hard,
    float* __restrict__ out_soft)
{
    extern __shared__ char smraw[];
    Smem& sm = *reinterpret_cast<Smem*>(smraw);
    const int tid  = threadIdx.x;
    const int lane = tid & 31, wid = tid >> 5;
    const int base_row = blockIdx.x * MT;

    // ---- stage xs (group0 for every thread) ----
    {
        const float4* src = reinterpret_cast<const float4*>(slots) + (size_t)base_row * (D_ / 4);
        #pragma unroll
        for (int t = 0; t < 32; t++) {
            int idx = tid + t * 256;
            int row = idx >> 6, c4 = idx & 63;
            cp16(&sm.xs[row * XSTR + c4 * 4], &src[idx]);
        }
        cp_commit();
    }
    // ---- per-path prestage of chunks 0 and 1 (groups 1,2 per thread) ----
    if (wid < 4) {
        int tl = tid;                                        // 0..127
        const float4* bh = reinterpret_cast<const float4*>(g_Bh);
        float4* d0 = reinterpret_cast<float4*>(sm.bufT[0]);
        float4* d1 = reinterpret_cast<float4*>(sm.bufT[1]);
        #pragma unroll
        for (int t = 0; t < 10; t++) cp16(&d0[tl + t * 128], &bh[0 * 1280 + tl + t * 128]);
        cp_commit();
        #pragma unroll
        for (int t = 0; t < 10; t++) cp16(&d1[tl + t * 128], &bh[1 * 1280 + tl + t * 128]);
        cp_commit();
    } else {
        int tl = tid - 128;                                  // 0..127
        const float4* wsrc = reinterpret_cast<const float4*>(w1);
        float4* d0 = reinterpret_cast<float4*>(sm.bufF[0]);
        float4* d1 = reinterpret_cast<float4*>(sm.bufF[1]);
        #pragma unroll
        for (int t = 0; t < 8; t++) cp16(&d0[tl + t * 128], &wsrc[0 * 1024 + tl + t * 128]);
        cp_commit();
        #pragma unroll
        for (int t = 0; t < 8; t++) cp16(&d1[tl + t * 128], &wsrc[1 * 1024 + tl + t * 128]);
        cp_commit();
    }
    sm.gs[tid]  = lng[tid];
    sm.bs[tid]  = lnb[tid];
    sm.b1s[tid] = b1[tid];
    sm.w2s[tid] = make_float2(w2[2 * tid], w2[2 * tid + 1]);
    if (tid == 0) sm.cnt = 0;

    cp_wait<2>();              // xs arrived (chunks 0/1 may still be in flight)
    __syncthreads();

    // ---- LayerNorm (all warps) ----
    for (int r = wid; r < MT; r += 8) {
        const float* row = sm.xs + r * XSTR;
        float s = 0.f;
        #pragma unroll
        for (int m = 0; m < 8; m++) s += row[lane + m * 32];
        #pragma unroll
        for (int o = 16; o; o >>= 1) s += __shfl_xor_sync(0xffffffffu, s, o);
        float mean = s * (1.f / D_);
        float v = 0.f;
        #pragma unroll
        for (int m = 0; m < 8; m++) { float d = row[lane + m * 32] - mean; v = fmaf(d, d, v); }
        #pragma unroll
        for (int o = 16; o; o >>= 1) v += __shfl_xor_sync(0xffffffffu, v, o);
        if (lane == 0) { sm.mu[r] = mean; sm.rs[r] = 1.f / sqrtf(v * (1.f / D_) + LN_EPS); }
    }
    __syncthreads();
    #pragma unroll 4
    for (int r = 0; r < MT; r++) {
        int idx = r * XSTR + tid;
        float vx = sm.xs[idx];
        sm.xs[idx] = (vx - sm.mu[r]) * sm.rs[r] * sm.gs[tid] + sm.bs[tid];
    }
    __syncthreads();

    float b20 = b2[0], b21 = b2[1];
    int mykept = 0;            // rows kept by THIS thread (0..2)

    if (wid < 4) {
        // ================= TENSOR PATH: rows 0..63, mma.sync TF32 3-split ========
        const int g = lane >> 2, tig = lane & 3;
        const int r0 = wid * 16 + g;                 // local rows r0 and r0+8
        float acc[32][4];
        #pragma unroll
        for (int nt = 0; nt < 32; nt++)
            #pragma unroll
            for (int q = 0; q < 4; q++) acc[nt][q] = 0.f;

        for (int s = 0; s < NCHT; s++) {
            const int b = s & 1;
            if (s == NCHT - 1) cp_wait<0>(); else cp_wait<1>();
            barx(2);

            const int seg = s >> 4, kc = s & 15;
            const uint32_t* bb = reinterpret_cast<const uint32_t*>(sm.bufT[b]);
            #pragma unroll
            for (int kk = 0; kk < KCHT; kk += 8) {
                int ck = kc * 16 + kk + tig;
                float x0 = sm.xs[r0 * XSTR + ck];
                float x1 = sm.xs[(r0 + 8) * XSTR + ck];
                float x2 = sm.xs[r0 * XSTR + ck + 4];
                float x3 = sm.xs[(r0 + 8) * XSTR + ck + 4];
                uint32_t a[4];
                if (seg == 2) {
                    uint32_t h0 = f2tf32(x0), h1 = f2tf32(x1), h2 = f2tf32(x2), h3 = f2tf32(x3);
                    a[0] = f2tf32(x0 - __uint_as_float(h0));
                    a[1] = f2tf32(x1 - __uint_as_float(h1));
                    a[2] = f2tf32(x2 - __uint_as_float(h2));
                    a[3] = f2tf32(x3 - __uint_as_float(h3));
                } else {
                    a[0] = f2tf32(x0); a[1] = f2tf32(x1);
                    a[2] = f2tf32(x2); a[3] = f2tf32(x3);
                }
                #pragma unroll
                for (int nt = 0; nt < 32; nt++) {
                    int nc = (nt * 8 + g) * KPADT;
                    uint32_t b0 = bb[nc + kk + tig];
                    uint32_t b1r = bb[nc + kk + tig + 4];
                    mma8(acc[nt], a, b0, b1r);
                }
            }
            barx(2);
            if (s + 2 < NCHT) {
                int ns = s + 2, nseg = ns >> 4, nkc = ns & 15;
                const float4* src = reinterpret_cast<const float4*>(nseg == 1 ? g_Bl : g_Bh)
                                  + nkc * 1280;
                float4* dst = reinterpret_cast<float4*>(sm.bufT[b]);
                #pragma unroll
                for (int t = 0; t < 10; t++) cp16(&dst[tid + t * 128], &src[tid + t * 128]);
                cp_commit();
            }
        }

        // epilogue: relu+b1, dot w2, quad-reduce, finalize rows r0 and r0+8
        float p0a = 0.f, p1a = 0.f, p0b = 0.f, p1b = 0.f;
        #pragma unroll
        for (int nt = 0; nt < 32; nt++)
            #pragma unroll
            for (int q = 0; q < 4; q++) {
                int cc = nt * 8 + tig * 2 + (q & 1);
                float h = fmaxf(acc[nt][q] + sm.b1s[cc], 0.f);
                float2 w = sm.w2s[cc];
                if (q < 2) { p0a = fmaf(h, w.x, p0a); p1a = fmaf(h, w.y, p1a); }
                else       { p0b = fmaf(h, w.x, p0b); p1b = fmaf(h, w.y, p1b); }
            }
        #pragma unroll
        for (int o = 1; o <= 2; o <<= 1) {
            p0a += __shfl_xor_sync(0xffffffffu, p0a, o);
            p1a += __shfl_xor_sync(0xffffffffu, p1a, o);
            p0b += __shfl_xor_sync(0xffffffffu, p0b, o);
            p1b += __shfl_xor_sync(0xffffffffu, p1b, o);
        }
        if (tig == 0) {
            #pragma unroll
            for (int half = 0; half < 2; half++) {
                int row = base_row + r0 + half * 8;
                float l0 = (half ? p0b : p0a) + b20;
                float l1 = (half ? p1b : p1a) + b21;
                float soft = 1.f / (1.f + expf(l0 - l1));
                float u0 = uu[2 * row], u1 = uu[2 * row + 1];
                float z0 = l0 - logf(-logf(u0));
                float z1 = l1 - logf(-logf(u1));
                int hard = (z1 > z0) ? 1 : 0;
                out_hard[row] = (float)hard;
                out_soft[row] = soft;
                mykept += hard;
                if (fabsf(z1 - z0) < TIE_EPS) {
                    int ix = atomicAdd(&g_tie_n, 1);
                    g_tie_rows[ix] = row;
                }
            }
        }
    } else {
        // ================= FMA PATH: rows 64..127, exact fp32 f32x2 ==============
        const int tl = tid - 128;
        const int tx = tl & 15, ty = tl >> 4;        // ty 0..7
        unsigned long long acc2[8][8];
        #pragma unroll
        for (int i = 0; i < 8; i++)
            #pragma unroll
            for (int p = 0; p < 8; p++) acc2[i][p] = 0ull;

        const float* xbase = sm.xs + (64 + ty * 8) * XSTR;
        const float4* wsrc = reinterpret_cast<const float4*>(w1);

        for (int c = 0; c < NCHF; c++) {
            const int b = c & 1;
            if (c == NCHF - 1) cp_wait<0>(); else cp_wait<1>();
            barx(1);

            const ulonglong2* wb2 = reinterpret_cast<const ulonglong2*>(sm.bufF[b]);
            #pragma unroll
            for (int kk = 0; kk < KCHF; kk += 4) {
                float4 a4[8];
                #pragma unroll
                for (int i = 0; i < 8; i++)
                    a4[i] = *reinterpret_cast<const float4*>(xbase + i * XSTR + c * KCHF + kk);
                #pragma unroll
                for (int t = 0; t < 4; t++) {
                    const ulonglong2* wrow = wb2 + (kk + t) * 64 + tx;
                    ulonglong2 q0 = wrow[0], q1 = wrow[16], q2 = wrow[32], q3 = wrow[48];
                    #pragma unroll
                    for (int i = 0; i < 8; i++) {
                        unsigned long long ap = bcast2((&a4[i].x)[t]);
                        ffma2(acc2[i][0], ap, q0.x);
                        ffma2(acc2[i][1], ap, q0.y);
                        ffma2(acc2[i][2], ap, q1.x);
                        ffma2(acc2[i][3], ap, q1.y);
                        ffma2(acc2[i][4], ap, q2.x);
                        ffma2(acc2[i][5], ap, q2.y);
                        ffma2(acc2[i][6], ap, q3.x);
                        ffma2(acc2[i][7], ap, q3.y);
                    }
                }
            }
            barx(1);
            if (c + 2 < NCHF) {
                float4* dst = reinterpret_cast<float4*>(sm.bufF[b]);
                #pragma unroll
                for (int t = 0; t < 8; t++)
                    cp16(&dst[tl + t * 128], &wsrc[(c + 2) * 1024 + tl + t * 128]);
                cp_commit();
            }
        }

        // epilogue (interleaved col map): pair p=2j+h -> cc = 4*(tx+16j)+2h
        #pragma unroll
        for (int i = 0; i < 8; i++) {
            float p0 = 0.f, p1 = 0.f;
            #pragma unroll
            for (int p = 0; p < 8; p++) {
                union { unsigned long long u; float2 f; } cvt;
                cvt.u = acc2[i][p];
                int j = p >> 1, h = p & 1;
                int cc = 4 * (tx + 16 * j) + 2 * h;
                float h0 = fmaxf(cvt.f.x + sm.b1s[cc], 0.f);
                float h1 = fmaxf(cvt.f.y + sm.b1s[cc + 1], 0.f);
                float2 wA = sm.w2s[cc];
                float2 wB = sm.w2s[cc + 1];
                p0 = fmaf(h0, wA.x, p0); p1 = fmaf(h0, wA.y, p1);
                p0 = fmaf(h1, wB.x, p0); p1 = fmaf(h1, wB.y, p1);
            }
            #pragma unroll
            for (int o = 8; o; o >>= 1) {
                p0 += __shfl_xor_sync(0xffffffffu, p0, o);
                p1 += __shfl_xor_sync(0xffffffffu, p1, o);
            }
            if (tx == i) {
                int row = base_row + 64 + ty * 8 + i;
                float l0 = p0 + b20, l1 = p1 + b21;
                float soft = 1.f / (1.f + expf(l0 - l1));
                float u0 = uu[2 * row], u1 = uu[2 * row + 1];
                float z0 = l0 - logf(-logf(u0));
                float z1 = l1 - logf(-logf(u1));
                int hard = (z1 > z0) ? 1 : 0;
                out_hard[row] = (float)hard;
                out_soft[row] = soft;
                mykept += hard;
            }
        }
    }

    // kept-count: warp reduce mykept, lane0 accumulates
    #pragma unroll
    for (int o = 16; o; o >>= 1) mykept += __shfl_xor_sync(0xffffffffu, mykept, o);
    if (lane == 0) atomicAdd(&sm.cnt, mykept);
    __syncthreads();
    if (tid == 0) g_partial[blockIdx.x] = sm.cnt;
}

// ---------------- cleanup: exact fp32 recompute of near-tie tensor rows ----------------
__global__ void __launch_bounds__(256) cleanup_kernel(
    const float* __restrict__ slots, const float* __restrict__ lng,
    const float* __restrict__ lnb,   const float* __restrict__ w1,
    const float* __restrict__ b1,    const float* __restrict__ w2,
    const float* __restrict__ b2,    const float* __restrict__ uu,
    float* __restrict__ out_hard,    float* __restrict__ out_soft)
{
    __shared__ float xln[256];
    __shared__ float wr[8], l0s[8], l1s[8];
    const int t = threadIdx.x, lane = t & 31, w = t >> 5;
    const int n = g_tie_n;
    for (int ii = blockIdx.x; ii < n; ii += gridDim.x) {
        int row = g_tie_rows[ii];
        float v = slots[(size_t)row * D_ + t];
        float s = v;
        #pragma unroll
        for (int o = 16; o; o >>= 1) s += __shfl_xor_sync(0xffffffffu, s, o);
        if (lane == 0) wr[w] = s;
        __syncthreads();
        float tot = 0.f;
        #pragma unroll
        for (int j = 0; j < 8; j++) tot += wr[j];
        float mean = tot * (1.f / 256);
        __syncthreads();
        float d = v - mean, s2 = d * d;
        #pragma unroll
        for (int o = 16; o; o >>= 1) s2 += __shfl_xor_sync(0xffffffffu, s2, o);
        if (lane == 0) wr[w] = s2;
        __syncthreads();
        float vt = 0.f;
        #pragma unroll
        for (int j = 0; j < 8; j++) vt += wr[j];
        float rstd = 1.f / sqrtf(vt * (1.f / 256) + LN_EPS);
        xln[t] = (v - mean) * rstd * lng[t] + lnb[t];
        __syncthreads();
        float acc = b1[t];
        for (int k = 0; k < 256; k++) acc = fmaf(xln[k], w1[k * 256 + t], acc);
        float h = fmaxf(acc, 0.f);
        float q0 = h * w2[2 * t], q1 = h * w2[2 * t + 1];
        #pragma unroll
        for (int o = 16; o; o >>= 1) {
            q0 += __shfl_xor_sync(0xffffffffu, q0, o);
            q1 += __shfl_xor_sync(0xffffffffu, q1, o);
        }
        if (lane == 0) { l0s[w] = q0; l1s[w] = q1; }
        __syncthreads();
        if (t == 0) {
            float l0 = b2[0], l1 = b2[1];
            #pragma unroll
            for (int j = 0; j < 8; j++) { l0 += l0s[j]; l1 += l1s[j]; }
            float soft = 1.f / (1.f + expf(l0 - l1));
            float u0 = uu[2 * row], u1 = uu[2 * row + 1];
            float z0 = l0 - logf(-logf(u0));
            float z1 = l1 - logf(-logf(u1));
            int hard = (z1 > z0) ? 1 : 0;
            int oldh = (out_hard[row] != 0.f) ? 1 : 0;
            if (hard != oldh) {
                out_hard[row] = (float)hard;
                atomicAdd(&g_partial[row >> 7], hard - oldh);
            }
            out_soft[row] = soft;
        }
        __syncthreads();
    }
}

// ---------------- resample: lower-bound fixup ----------------
__global__ void __launch_bounds__(256) resample_kernel(
    const float* __restrict__ rk, float* __restrict__ out_hard)
{
    __shared__ float vs[256];
    __shared__ int   is_[256];
    const int b = blockIdx.x, tid = threadIdx.x;
    int kept = 0;
    #pragma unroll
    for (int j = 0; j < BPB; j++) kept += g_partial[b * BPB + j];
    if (kept > 0) return;
    const float* r = rk + b * K_;
    float v0 = r[tid], v1 = r[tid + 256];
    float v; int idx;
    if (v0 >= v1) { v = v0; idx = tid; } else { v = v1; idx = tid + 256; }
    vs[tid] = v; is_[tid] = idx;
    __syncthreads();
    for (int s = 128; s; s >>= 1) {
        if (tid < s) {
            float ov = vs[tid + s]; int oi = is_[tid + s];
            if (ov > vs[tid] || (ov == vs[tid] && oi < is_[tid])) { vs[tid] = ov; is_[tid] = oi; }
        }
        __syncthreads();
    }
    if (tid == 0) out_hard[b * K_ + is_[0]] = 1.f;
}

extern "C" void kernel_launch(void* const* d_in, const int* in_sizes, int n_in,
                              void* d_out, int out_size)
{
    const float* slots = (const float*)d_in[0];
    const float* lng   = (const float*)d_in[1];
    const float* lnb   = (const float*)d_in[2];
    const float* w1    = (const float*)d_in[3];
    const float* b1    = (const float*)d_in[4];
    const float* w2    = (const float*)d_in[5];
    const float* b2    = (const float*)d_in[6];
    const float* uu    = (const float*)d_in[7];
    const float* rk    = (const float*)d_in[8];
    float* out_hard = (float*)d_out;
    float* out_soft = out_hard + BK;

    cudaFuncSetAttribute(fused_kernel,
                         cudaFuncAttributeMaxDynamicSharedMemorySize,
                         (int)sizeof(Smem));

    prep_kernel<<<256, 256>>>(w1);
    fused_kernel<<<NBLK, 256, sizeof(Smem)>>>(slots, lng, lnb, w1, b1, w2, b2,
                                              uu, out_hard, out_soft);
    cleanup_kernel<<<64, 256>>>(slots, lng, lnb, w1, b1, w2, b2, uu,
                                out_hard, out_soft);
    resample_kernel<<<B_, 256>>>(rk, out_hard);
}